// round 14
// baseline (speedup 1.0000x reference)
#include <cuda_runtime.h>
#include <cuda_fp16.h>
#include <mma.h>
#include <math.h>

using namespace nvcuda;

#define N_NODES   40000
#define N_EDGES   640000
#define FDIM      128
#define N_GRAPHS  64
#define N_CLASSES 10
#define MAXDEG    64        // Poisson(16) in-degree; P(>=64) ~ 1e-20

#define GEMM_BM   128
#define GEMM_NB   ((N_NODES + GEMM_BM - 1) / GEMM_BM)   // 313
#define N_PADROWS (GEMM_NB * GEMM_BM)                   // 40064

// ---------------- scratch (device globals; no allocations) ------------------
__device__ __align__(16) __half g_A16[N_PADROWS * FDIM];
__device__ __align__(16) __half g_B16[N_PADROWS * FDIM];
__device__ int    g_indeg[N_NODES];
__device__ float  g_dis[N_NODES];
__device__ int    g_src[N_NODES * MAXDEG];   // padded CSR: srcs of in-edges
__device__ float  g_sums[N_GRAPHS * FDIM];
__device__ float  g_cnts[N_GRAPHS];

// ---------------- init: zero indeg + pool sums ------------------------------
__global__ void init_kernel() {
    int i = blockIdx.x * blockDim.x + threadIdx.x;
    if (i < N_NODES) g_indeg[i] = 0;
    if (i < N_GRAPHS * FDIM) g_sums[i] = 0.f;
    if (i < N_GRAPHS) g_cnts[i] = 0.f;
}

// ---------------- single-pass padded-CSR fill --------------------------------
__global__ void fill_direct_kernel(const int* __restrict__ row,
                                   const int* __restrict__ col) {
    int e = blockIdx.x * blockDim.x + threadIdx.x;
    if (e >= N_EDGES) return;
    int r = row[e];
    int c = col[e];
    int p = atomicAdd(&g_indeg[c], 1);
    if (p < MAXDEG) g_src[c * MAXDEG + p] = r;
}

// ---------------- dis = rsqrt(deg+1) -----------------------------------------
__global__ void dis_kernel() {
    int i = blockIdx.x * blockDim.x + threadIdx.x;
    if (i < N_NODES) g_dis[i] = rsqrtf((float)(g_indeg[i] + 1));
}

// ---------------- shared helpers ---------------------------------------------
__device__ __forceinline__ float4 h4_to_f4(uint2 u) {
    __half2 a = *(__half2*)&u.x;
    __half2 b = *(__half2*)&u.y;
    float2 fa = __half22float2(a);
    float2 fb = __half22float2(b);
    return make_float4(fa.x, fa.y, fb.x, fb.y);
}

// ---------------- GEMM: BM=128 tile, 256 thr, 1.06 waves ---------------------
#define LDP      136
#define GEMM_SMEM_BYTES ((2 * 128 * LDP + GEMM_BM * LDP) * 2)   // ~104.4 KB

__device__ __forceinline__ void stage_w_split(const float* __restrict__ W,
                                              __half* Wh, __half* Wl, int tid) {
    const float4* W4 = (const float4*)W;
#pragma unroll
    for (int i = 0; i < 16; i++) {
        int idx = tid + 256 * i;
        float4 w = W4[idx];
        int r = idx >> 5, c = (idx & 31) * 4;
        __half h0 = __float2half_rn(w.x);
        __half h1 = __float2half_rn(w.y);
        __half h2 = __float2half_rn(w.z);
        __half h3 = __float2half_rn(w.w);
        __half l0 = __float2half_rn(w.x - __half2float(h0));
        __half l1 = __float2half_rn(w.y - __half2float(h1));
        __half l2 = __float2half_rn(w.z - __half2float(h2));
        __half l3 = __float2half_rn(w.w - __half2float(h3));
        __half2 hh0 = __halves2half2(h0, h1);
        __half2 hh1 = __halves2half2(h2, h3);
        __half2 ll0 = __halves2half2(l0, l1);
        __half2 ll1 = __halves2half2(l2, l3);
        uint2 uh; uh.x = *(unsigned*)&hh0; uh.y = *(unsigned*)&hh1;
        uint2 ul; ul.x = *(unsigned*)&ll0; ul.y = *(unsigned*)&ll1;
        *(uint2*)(Wh + r * LDP + c) = uh;
        *(uint2*)(Wl + r * LDP + c) = ul;
    }
}

template <bool XF32>
__global__ __launch_bounds__(256, 2)
void gemm_wmma_kernel(const void* __restrict__ Xv,
                      const float* __restrict__ W,
                      __half* __restrict__ Y) {
    extern __shared__ __half smh[];
    __half* Wh = smh;
    __half* Wl = smh + 128 * LDP;
    __half* Xs = smh + 2 * 128 * LDP;

    int tid  = threadIdx.x;
    int row0 = blockIdx.x * GEMM_BM;

    stage_w_split(W, Wh, Wl, tid);

    if (XF32) {
        // 128 rows x 128 f32 = 4096 float4; guard tail-block reads (x exact-sized)
        const float4* X4 = (const float4*)((const float*)Xv + (size_t)row0 * FDIM);
        int maxv4 = (N_NODES - row0) * 32;      // valid float4 count
#pragma unroll
        for (int i = 0; i < 16; i++) {
            int idx = tid + 256 * i;
            float4 v = (idx < maxv4) ? X4[idx] : make_float4(0.f, 0.f, 0.f, 0.f);
            int r = idx >> 5, c = (idx & 31) * 4;
            __half2 h0 = __floats2half2_rn(v.x, v.y);
            __half2 h1 = __floats2half2_rn(v.z, v.w);
            uint2 u; u.x = *(unsigned*)&h0; u.y = *(unsigned*)&h1;
            *(uint2*)(Xs + r * LDP + c) = u;
        }
    } else {
        // fp16 input from padded buffer: no guard needed
        const float4* X4 = (const float4*)((const __half*)Xv + (size_t)row0 * FDIM);
#pragma unroll
        for (int i = 0; i < 8; i++) {
            int idx = tid + 256 * i;
            int r = idx >> 4, c8 = idx & 15;
            *(float4*)(Xs + r * LDP + c8 * 8) = X4[idx];
        }
    }
    __syncthreads();

    int warp = tid >> 5;
    int wr = warp >> 1;        // 0..3 : rows wr*32 .. +32 (2 m-tiles)
    int wc = warp & 1;         // 0..1 : cols wc*64 .. +64 (4 n-tiles)

    wmma::fragment<wmma::matrix_a, 16, 16, 16, __half, wmma::row_major> a0, a1;
    wmma::fragment<wmma::matrix_b, 16, 16, 16, __half, wmma::row_major> bh, bl;
    wmma::fragment<wmma::accumulator, 16, 16, 16, float> acc[2][4];
#pragma unroll
    for (int m = 0; m < 2; m++)
#pragma unroll
        for (int j = 0; j < 4; j++) wmma::fill_fragment(acc[m][j], 0.0f);

#pragma unroll
    for (int kk = 0; kk < 8; kk++) {
        wmma::load_matrix_sync(a0, Xs + (wr * 32) * LDP + kk * 16, LDP);
        wmma::load_matrix_sync(a1, Xs + (wr * 32 + 16) * LDP + kk * 16, LDP);
#pragma unroll
        for (int j = 0; j < 4; j++) {
            int coff = wc * 64 + j * 16;
            wmma::load_matrix_sync(bh, Wh + (kk * 16) * LDP + coff, LDP);
            wmma::mma_sync(acc[0][j], a0, bh, acc[0][j]);
            wmma::mma_sync(acc[1][j], a1, bh, acc[1][j]);
            wmma::load_matrix_sync(bl, Wl + (kk * 16) * LDP + coff, LDP);
            wmma::mma_sync(acc[0][j], a0, bl, acc[0][j]);
            wmma::mma_sync(acc[1][j], a1, bl, acc[1][j]);
        }
    }

#pragma unroll
    for (int m = 0; m < 2; m++)
#pragma unroll
    for (int j = 0; j < 4; j++) {
        wmma::fragment<wmma::accumulator, 16, 16, 16, __half> hfrag;
#pragma unroll
        for (int t = 0; t < hfrag.num_elements; t++)
            hfrag.x[t] = __float2half_rn(acc[m][j].x[t]);
        wmma::store_matrix_sync(
            Y + (size_t)(row0 + wr * 32 + m * 16) * FDIM + wc * 64 + j * 16,
            hfrag, FDIM, wmma::mem_row_major);   // Y padded: tail writes land in pad
    }
}

// ---------------- CSR gather (R7 loop shape; weight = dis[src], dis[c] folded)
template <int POOL>
__global__ void gather_kernel(const float* __restrict__ bias,
                              const int* __restrict__ batch) {
    int node = blockIdx.x * (blockDim.x >> 5) + (threadIdx.x >> 5);
    if (node >= N_NODES) return;
    int lane = threadIdx.x & 31;

    const uint2* B2 = (const uint2*)g_B16;

    int beg = node * MAXDEG;
    int deg = g_indeg[node];
    if (deg > MAXDEG) deg = MAXDEG;

    float dn = g_dis[node];
    float4 sv = h4_to_f4(B2[(size_t)node * 32 + lane]);
    float4 acc = make_float4(sv.x * dn, sv.y * dn, sv.z * dn, sv.w * dn);

    for (int base = 0; base < deg; base += 32) {
        int rem = deg - base; if (rem > 32) rem = 32;
        int   mysrc = 0;
        float myw   = 0.f;
        if (lane < rem) {
            mysrc = __ldg(&g_src[beg + base + lane]);
            myw   = __ldg(&g_dis[mysrc]);
        }

        int j = 0;
        for (; j + 4 <= rem; j += 4) {
            int   s0 = __shfl_sync(0xffffffffu, mysrc, j);
            int   s1 = __shfl_sync(0xffffffffu, mysrc, j + 1);
            int   s2 = __shfl_sync(0xffffffffu, mysrc, j + 2);
            int   s3 = __shfl_sync(0xffffffffu, mysrc, j + 3);
            float w0 = __shfl_sync(0xffffffffu, myw, j);
            float w1 = __shfl_sync(0xffffffffu, myw, j + 1);
            float w2 = __shfl_sync(0xffffffffu, myw, j + 2);
            float w3 = __shfl_sync(0xffffffffu, myw, j + 3);
            float4 v0 = h4_to_f4(__ldg(&B2[(size_t)s0 * 32 + lane]));
            float4 v1 = h4_to_f4(__ldg(&B2[(size_t)s1 * 32 + lane]));
            float4 v2 = h4_to_f4(__ldg(&B2[(size_t)s2 * 32 + lane]));
            float4 v3 = h4_to_f4(__ldg(&B2[(size_t)s3 * 32 + lane]));
            acc.x = fmaf(w0, v0.x, acc.x); acc.y = fmaf(w0, v0.y, acc.y);
            acc.z = fmaf(w0, v0.z, acc.z); acc.w = fmaf(w0, v0.w, acc.w);
            acc.x = fmaf(w1, v1.x, acc.x); acc.y = fmaf(w1, v1.y, acc.y);
            acc.z = fmaf(w1, v1.z, acc.z); acc.w = fmaf(w1, v1.w, acc.w);
            acc.x = fmaf(w2, v2.x, acc.x); acc.y = fmaf(w2, v2.y, acc.y);
            acc.z = fmaf(w2, v2.z, acc.z); acc.w = fmaf(w2, v2.w, acc.w);
            acc.x = fmaf(w3, v3.x, acc.x); acc.y = fmaf(w3, v3.y, acc.y);
            acc.z = fmaf(w3, v3.z, acc.z); acc.w = fmaf(w3, v3.w, acc.w);
        }
        for (; j < rem; j++) {
            int   s = __shfl_sync(0xffffffffu, mysrc, j);
            float w = __shfl_sync(0xffffffffu, myw, j);
            float4 v = h4_to_f4(__ldg(&B2[(size_t)s * 32 + lane]));
            acc.x = fmaf(w, v.x, acc.x); acc.y = fmaf(w, v.y, acc.y);
            acc.z = fmaf(w, v.z, acc.z); acc.w = fmaf(w, v.w, acc.w);
        }
    }

    float4 bv = __ldg(&((const float4*)bias)[lane]);
    acc.x = fmaxf(fmaf(dn, acc.x, bv.x), 0.f);
    acc.y = fmaxf(fmaf(dn, acc.y, bv.y), 0.f);
    acc.z = fmaxf(fmaf(dn, acc.z, bv.z), 0.f);
    acc.w = fmaxf(fmaf(dn, acc.w, bv.w), 0.f);

    if (POOL) {
        int g = __ldg(&batch[node]);
        float* dst = g_sums + (size_t)g * FDIM + lane * 4;
        asm volatile("red.global.add.v4.f32 [%0], {%1, %2, %3, %4};"
                     :: "l"(dst), "f"(acc.x), "f"(acc.y), "f"(acc.z), "f"(acc.w)
                     : "memory");
        if (lane == 0) atomicAdd(&g_cnts[g], 1.0f);
    } else {
        __half2 h0 = __floats2half2_rn(acc.x, acc.y);
        __half2 h1 = __floats2half2_rn(acc.z, acc.w);
        uint2 u; u.x = *(unsigned*)&h0; u.y = *(unsigned*)&h1;
        ((uint2*)g_A16)[(size_t)node * 32 + lane] = u;
    }
}

// ---------------- final linear ----------------------------------------------
__global__ void final_kernel(const float* __restrict__ Wl,
                             const float* __restrict__ bl,
                             float* __restrict__ out) {
    int g = blockIdx.x;
    int c = threadIdx.x;
    if (c >= N_CLASSES) return;
    float cnt = g_cnts[g];
    float inv = 1.0f / fmaxf(cnt, 1.0f);
    float acc = bl[c];
    for (int k = 0; k < FDIM; k++)
        acc += (g_sums[g * FDIM + k] * inv) * Wl[k * N_CLASSES + c];
    out[g * N_CLASSES + c] = acc;
}

// ---------------- launch ----------------------------------------------------
extern "C" void kernel_launch(void* const* d_in, const int* in_sizes, int n_in,
                              void* d_out, int out_size) {
    const float* x   = (const float*)d_in[0];
    const int*   ei  = (const int*)d_in[1];
    const int*   bat = (const int*)d_in[2];
    const float* W1  = (const float*)d_in[3];
    const float* b1  = (const float*)d_in[4];
    const float* W2  = (const float*)d_in[5];
    const float* b2  = (const float*)d_in[6];
    const float* W3  = (const float*)d_in[7];
    const float* b3  = (const float*)d_in[8];
    const float* Wl  = (const float*)d_in[9];
    const float* bl  = (const float*)d_in[10];
    float* out = (float*)d_out;

    const int* row = ei;
    const int* col = ei + N_EDGES;

    static cudaStream_t s1 = nullptr;
    static cudaEvent_t  ev_fork = nullptr, ev_join = nullptr;
    if (!s1) {
        cudaFuncSetAttribute(gemm_wmma_kernel<true>,
                             cudaFuncAttributeMaxDynamicSharedMemorySize,
                             GEMM_SMEM_BYTES);
        cudaFuncSetAttribute(gemm_wmma_kernel<false>,
                             cudaFuncAttributeMaxDynamicSharedMemorySize,
                             GEMM_SMEM_BYTES);
        cudaStreamCreateWithFlags(&s1, cudaStreamNonBlocking);
        cudaEventCreateWithFlags(&ev_fork, cudaEventDisableTiming);
        cudaEventCreateWithFlags(&ev_join, cudaEventDisableTiming);
    }

    const int node_warp_blocks = (N_NODES + 7) / 8;

    __half* A16; cudaGetSymbolAddress((void**)&A16, g_A16);
    __half* B16; cudaGetSymbolAddress((void**)&B16, g_B16);

    // fork: single-pass CSR build on side stream (3 launches)
    cudaEventRecord(ev_fork, 0);
    cudaStreamWaitEvent(s1, ev_fork, 0);

    init_kernel<<<(N_NODES + 255) / 256, 256, 0, s1>>>();
    fill_direct_kernel<<<(N_EDGES + 255) / 256, 256, 0, s1>>>(row, col);
    dis_kernel<<<(N_NODES + 255) / 256, 256, 0, s1>>>();
    cudaEventRecord(ev_join, s1);

    // main stream: layer-1 GEMM reads fp32 x directly
    gemm_wmma_kernel<true><<<GEMM_NB, 256, GEMM_SMEM_BYTES>>>(x, W1, B16);
    cudaStreamWaitEvent(0, ev_join, 0);

    gather_kernel<0><<<node_warp_blocks, 256>>>(b1, bat);
    gemm_wmma_kernel<false><<<GEMM_NB, 256, GEMM_SMEM_BYTES>>>(A16, W2, B16);
    gather_kernel<0><<<node_warp_blocks, 256>>>(b2, bat);
    gemm_wmma_kernel<false><<<GEMM_NB, 256, GEMM_SMEM_BYTES>>>(A16, W3, B16);
    gather_kernel<1><<<node_warp_blocks, 256>>>(b3, bat);

    final_kernel<<<N_GRAPHS, 32>>>(Wl, bl, out);
}